// round 1
// baseline (speedup 1.0000x reference)
#include <cuda_runtime.h>

#define R_GAS   8.3144621f
#define F_CONST 96487.0f
#define ALPHA   0.5f
#define SN_C    0.000437545f
#define SP_C    0.00030962f
#define KN_C    2120.96f
#define KP_C    248898.0f
#define RO_C    0.117215f
#define T_DIFF  7000000.0f
#define T_O     6.08671f
#define T_SN    1001.38f
#define T_SP    46.4311f
#define U0P     4.03f
#define U0N     0.01f
#define DT      1.0f
#define Q_MAX   (7600.0f / 0.6f)
#define VOL     2e-05f
#define VOL_S   (0.1f * VOL)
#define VOL_B   (VOL - VOL_S)
#define Q_S_MAX (Q_MAX * VOL_S / VOL)

__device__ __constant__ float AP_C[13] = {
    -31593.7f, 0.106747f, 24606.4f, -78561.9f, 13317.9f, 307387.0f,
    84916.1f, -1074690.0f, 2285.04f, 990894.0f, 283920.0f, -161513.0f, -469218.0f
};
#define AN0 86.19f

// Full 13-term series for the P electrode.
__device__ __forceinline__ float ve_sum_p(float x) {
    float m  = 2.0f * x - 1.0f;
    float s  = AP_C[0] * m;
    float pw = 1.0f;
    float m2 = m * m;
    float tx = 2.0f * x * (1.0f - x);
#pragma unroll
    for (int k = 1; k < 13; ++k) {
        s  = fmaf(AP_C[k] * pw, m2 - tx * (float)k, s);
        pw = pw * m;
    }
    return s / F_CONST;
}

__global__ void __launch_bounds__(256)
battery_cell_kernel(const float* __restrict__ inp,
                    const float* __restrict__ states,
                    float* __restrict__ out, int B)
{
    int t = blockIdx.x * blockDim.x + threadIdx.x;
    if (t >= B) return;

    // states row: 8 contiguous floats -> two float4 loads (coalesced)
    const float4* s4 = reinterpret_cast<const float4*>(states) + 2 * t;
    float4 a = s4[0];
    float4 b = s4[1];
    float Tb = a.x, Vo = a.y, Vsn = a.z, Vsp = a.w;
    float qnB = b.x, qnS = b.y, qpB = b.z, qpS = b.w;
    float i = inp[t];

    float xnS = qnS / Q_S_MAX;
    float xpS = qpS / Q_S_MAX;

    float qdDn = (qnB / VOL_B - qnS / VOL_S) / T_DIFF;
    float qdDp = (qpB / VOL_B - qpS / VOL_S) / T_DIFF;

    // pow(x, 0.5) == sqrt(x)
    float Jn0 = KN_C * sqrtf(1.0f - xnS) * sqrtf(xnS);
    float Jp0 = KP_C * sqrtf(1.0f - xpS) * sqrtf(xpS);

    float Jn = i / SN_C;
    float Jp = i / SP_C;

    float rtfa = R_GAS * Tb / F_CONST / ALPHA;
    float VsnNom = rtfa * asinhf(Jn / (2.0f * Jn0));
    float VspNom = rtfa * asinhf(Jp / (2.0f * Jp0));

    float Tb_n  = Tb;
    float Vo_n  = Vo  + (i * RO_C - Vo)  / T_O  * DT;
    float Vsn_n = Vsn + (VsnNom - Vsn)   / T_SN * DT;
    float Vsp_n = Vsp + (VspNom - Vsp)   / T_SP * DT;
    float qnB_n = qnB - qdDn * DT;
    float qnS_n = qnS + (qdDn - i) * DT;
    float qpB_n = qpB - qdDp * DT;
    float qpS_n = qpS + (i + qdDp) * DT;

    float xnS2 = qnS_n / Q_S_MAX;
    float xpS2 = qpS_n / Q_S_MAX;

    float rtf = R_GAS * Tb_n / F_CONST;
    // AN: only A[0] != 0 -> series = A0*m/F
    float mN  = 2.0f * xnS2 - 1.0f;
    float Ven = U0N + rtf * logf((1.0f - xnS2) / xnS2) + (AN0 * mN) / F_CONST;
    float Vep = U0P + rtf * logf((1.0f - xpS2) / xpS2) + ve_sum_p(xpS2);

    float V = Vep - Ven - Vo_n - Vsn_n - Vsp_n;

    // Output: Z (B,2) then X_next (B,8)
    float2* z2 = reinterpret_cast<float2*>(out) + t;
    z2[0] = make_float2(Tb_n - 273.15f, V);

    float4* x4 = reinterpret_cast<float4*>(out + 2LL * B) + 2 * t;
    x4[0] = make_float4(Tb_n, Vo_n, Vsn_n, Vsp_n);
    x4[1] = make_float4(qnB_n, qnS_n, qpB_n, qpS_n);
}

extern "C" void kernel_launch(void* const* d_in, const int* in_sizes, int n_in,
                              void* d_out, int out_size)
{
    const float* inp    = (const float*)d_in[0];   // (B,1)
    const float* states = (const float*)d_in[1];   // (B,8)
    int B = in_sizes[0];
    float* out = (float*)d_out;                    // Z (B,2) ++ X_next (B,8)

    int threads = 256;
    int blocks = (B + threads - 1) / threads;
    battery_cell_kernel<<<blocks, threads>>>(inp, states, out, B);
}

// round 2
// speedup vs baseline: 1.3344x; 1.3344x over previous
#include <cuda_runtime.h>

#define R_GAS   8.3144621f
#define F_CONST 96487.0f
#define ALPHA   0.5f
#define SN_C    0.000437545f
#define SP_C    0.00030962f
#define KN_C    2120.96f
#define KP_C    248898.0f
#define RO_C    0.117215f
#define T_O     6.08671f
#define T_SN    1001.38f
#define T_SP    46.4311f
#define U0P     4.03f
#define U0N     0.01f
#define Q_MAX   (7600.0f / 0.6f)
#define VOL     2e-05f
#define VOL_S   (0.1f * VOL)
#define VOL_B   (VOL - VOL_S)
#define Q_S_MAX (Q_MAX * VOL_S / VOL)

// Reciprocal constants (compile-time folded)
#define INV_QSMAX  (1.0f / Q_S_MAX)
#define INV_VOLB   (1.0f / VOL_B)
#define INV_VOLS   (1.0f / VOL_S)
#define INV_TDIFF  (1.0f / T_DIFF_)
#define T_DIFF_    7000000.0f
#define INV_TO     (1.0f / T_O)
#define INV_TSN    (1.0f / T_SN)
#define INV_TSP    (1.0f / T_SP)
#define INV_F      (1.0f / F_CONST)
#define RTF_C      (R_GAS / F_CONST)          // R/F
#define RTFA_C     (R_GAS / F_CONST / ALPHA)  // R/F/alpha
// asinh arg = i/(SN * 2 * KN * sqrt(x(1-x))) = i * CN * rsqrt(x(1-x))
#define CN_C       (1.0f / (SN_C * 2.0f * KN_C))
#define CP_C       (1.0f / (SP_C * 2.0f * KP_C))
#define AN0_F      (86.19f / F_CONST)

__device__ __constant__ float AP_C[13] = {
    -31593.7f, 0.106747f, 24606.4f, -78561.9f, 13317.9f, 307387.0f,
    84916.1f, -1074690.0f, 2285.04f, 990894.0f, 283920.0f, -161513.0f, -469218.0f
};

// 13-term series for the P electrode (fully unrolled FMAs).
__device__ __forceinline__ float ve_sum_p(float x) {
    float m  = 2.0f * x - 1.0f;
    float s  = AP_C[0] * m;
    float pw = 1.0f;
    float m2 = m * m;
    float tx = 2.0f * x * (1.0f - x);
#pragma unroll
    for (int k = 1; k < 13; ++k) {
        s  = fmaf(AP_C[k] * pw, fmaf(-tx, (float)k, m2), s);
        pw = pw * m;
    }
    return s * INV_F;
}

// asinh(y) for y > 0, fast path: log(y + sqrt(y^2+1)) via MUFU.LG2
__device__ __forceinline__ float fast_asinh_pos(float y) {
    return __logf(y + sqrtf(fmaf(y, y, 1.0f)));
}

__global__ void __launch_bounds__(256)
battery_cell_kernel(const float* __restrict__ inp,
                    const float* __restrict__ states,
                    float* __restrict__ out, int B)
{
    int t = blockIdx.x * blockDim.x + threadIdx.x;
    if (t >= B) return;

    const float4* s4 = reinterpret_cast<const float4*>(states) + 2 * t;
    float4 a = s4[0];
    float4 b = s4[1];
    float Tb = a.x, Vo = a.y, Vsn = a.z, Vsp = a.w;
    float qnB = b.x, qnS = b.y, qpB = b.z, qpS = b.w;
    float i = inp[t];

    float xnS = qnS * INV_QSMAX;
    float xpS = qpS * INV_QSMAX;

    float qdDn = (qnB * INV_VOLB - qnS * INV_VOLS) * INV_TDIFF;
    float qdDp = (qpB * INV_VOLB - qpS * INV_VOLS) * INV_TDIFF;

    // asinh argument: Jn/(2*Jn0) = i * CN * rsqrt(xnS*(1-xnS))
    float argN = i * CN_C * rsqrtf(xnS * (1.0f - xnS));
    float argP = i * CP_C * rsqrtf(xpS * (1.0f - xpS));

    float rtfa   = RTFA_C * Tb;
    float VsnNom = rtfa * fast_asinh_pos(argN);
    float VspNom = rtfa * fast_asinh_pos(argP);

    float Tb_n  = Tb;
    float Vo_n  = Vo  + (fmaf(i, RO_C, -Vo)) * INV_TO;
    float Vsn_n = Vsn + (VsnNom - Vsn) * INV_TSN;
    float Vsp_n = Vsp + (VspNom - Vsp) * INV_TSP;
    float qnB_n = qnB - qdDn;
    float qnS_n = qnS + (qdDn - i);
    float qpB_n = qpB - qdDp;
    float qpS_n = qpS + (i + qdDp);

    float xnS2 = qnS_n * INV_QSMAX;
    float xpS2 = qpS_n * INV_QSMAX;

    float rtf = RTF_C * Tb_n;
    float mN  = 2.0f * xnS2 - 1.0f;
    float Ven = U0N + rtf * __logf(__fdividef(1.0f - xnS2, xnS2)) + AN0_F * mN;
    float Vep = U0P + rtf * __logf(__fdividef(1.0f - xpS2, xpS2)) + ve_sum_p(xpS2);

    float V = Vep - Ven - Vo_n - Vsn_n - Vsp_n;

    // Output: Z (B,2) then X_next (B,8)
    float2* z2 = reinterpret_cast<float2*>(out) + t;
    z2[0] = make_float2(Tb_n - 273.15f, V);

    float4* x4 = reinterpret_cast<float4*>(out + 2LL * B) + 2 * t;
    x4[0] = make_float4(Tb_n, Vo_n, Vsn_n, Vsp_n);
    x4[1] = make_float4(qnB_n, qnS_n, qpB_n, qpS_n);
}

extern "C" void kernel_launch(void* const* d_in, const int* in_sizes, int n_in,
                              void* d_out, int out_size)
{
    const float* inp    = (const float*)d_in[0];   // (B,1)
    const float* states = (const float*)d_in[1];   // (B,8)
    int B = in_sizes[0];
    float* out = (float*)d_out;                    // Z (B,2) ++ X_next (B,8)

    int threads = 256;
    int blocks = (B + threads - 1) / threads;
    battery_cell_kernel<<<blocks, threads>>>(inp, states, out, B);
}